// round 4
// baseline (speedup 1.0000x reference)
#include <cuda_runtime.h>
#include <cuda_fp16.h>
#include <cstdint>

#define D 128
#define NN 50000
#define NE 500000
#define TILE_M 128

// ---------------- scratch (__device__ globals) ------------------------------
__device__ float g_psrc[(size_t)NN * D];
__device__ float g_ptgt[(size_t)NN * D];
__device__ float g_agg [(size_t)NN * D];
// fp16 hi/lo weight images in the exact swizzled smem layout: [5][hi 32KB][lo 32KB]
__device__ unsigned char g_wimg[5 * 65536];

// ---------------- smem layout ----------------------------------------------
#define SM_XHI 0
#define SM_XLO 32768
#define SM_WHI 65536
#define SM_WLO 98304
#define SM_RED 131072               // float2 red[128][2] = 2KB
#define SM_TOTAL (131072 + 2048)

// swizzled fp16 tile: row r (0..127) x col c (0..127); 256B/row, 16B chunks
// chunk index (c>>3) XOR (r&7)  -> conflict-free ldmatrix
__device__ __forceinline__ uint32_t xswz(int r, int c) {
    return (uint32_t)(r * 256 + (((c >> 3) ^ (r & 7)) << 4) + (c & 7) * 2);
}

#define LDSM4(r, a) \
    asm volatile("ldmatrix.sync.aligned.m8n8.x4.shared.b16 {%0,%1,%2,%3}, [%4];" \
        : "=r"((r)[0]), "=r"((r)[1]), "=r"((r)[2]), "=r"((r)[3]) : "r"(a))
#define LDSM2(r, a) \
    asm volatile("ldmatrix.sync.aligned.m8n8.x2.shared.b16 {%0,%1}, [%2];" \
        : "=r"((r)[0]), "=r"((r)[1]) : "r"(a))
#define MMA(c, a, b) \
    asm volatile("mma.sync.aligned.m16n8k16.row.col.f32.f16.f16.f32 " \
        "{%0,%1,%2,%3}, {%4,%5,%6,%7}, {%8,%9}, {%0,%1,%2,%3};" \
        : "+f"((c)[0]), "+f"((c)[1]), "+f"((c)[2]), "+f"((c)[3]) \
        : "r"((a)[0]), "r"((a)[1]), "r"((a)[2]), "r"((a)[3]), "r"((b)[0]), "r"((b)[1]))

__device__ __forceinline__ uint32_t smem_u32(const void* p) {
    uint32_t a;
    asm("{ .reg .u64 t; cvta.to.shared.u64 t, %1; cvt.u32.u64 %0, t; }" : "=r"(a) : "l"(p));
    return a;
}
__device__ __forceinline__ unsigned short h_us(__half h) { return __half_as_ushort(h); }
__device__ __forceinline__ float silu(float m) { return m * (1.f / (1.f + __expf(-m))); }

// ---------------------------------------------------------------------------
__global__ void k_zero() {
    size_t i = ((size_t)blockIdx.x * blockDim.x + threadIdx.x) * 4;
    if (i < (size_t)NN * D) *(float4*)(g_agg + i) = make_float4(0.f, 0.f, 0.f, 0.f);
}

// prep: W [N,K] row-major -> swizzled fp16 hi/lo images (B operand, K-major)
__global__ void k_prep(const float* __restrict__ s2e, const float* __restrict__ t2e,
                       const float* __restrict__ e2e, const float* __restrict__ e2t,
                       const float* __restrict__ t2t) {
    const float* W[5] = {s2e, t2e, e2e, e2t, t2t};
    const float* src = W[blockIdx.x];
    unsigned char* hi = g_wimg + (size_t)blockIdx.x * 65536;
    unsigned char* lo = hi + 32768;
    for (int i = threadIdx.x; i < D * D; i += blockDim.x) {
        int n = i >> 7, k = i & 127;
        float w = src[i];
        __half h = __float2half_rn(w);
        __half l = __float2half_rn(w - __half2float(h));
        uint32_t off = xswz(n, k);
        *(__half*)(hi + off) = h;
        *(__half*)(lo + off) = l;
    }
}

// convert fp32 tile [128 x 128] -> split hi/lo fp16 in swizzled smem
__device__ __forceinline__ void convert_tile(const float* __restrict__ src, int row0,
                                             int nrows, char* a_hi, char* a_lo) {
    for (int i = threadIdx.x; i < TILE_M * 32; i += 256) {
        int r = i >> 5;
        int c = (i & 31) << 2;
        float4 v = make_float4(0.f, 0.f, 0.f, 0.f);
        if (row0 + r < nrows) v = *(const float4*)(src + (size_t)(row0 + r) * D + c);
        __half h0 = __float2half_rn(v.x), h1 = __float2half_rn(v.y);
        __half h2 = __float2half_rn(v.z), h3 = __float2half_rn(v.w);
        __half l0 = __float2half_rn(v.x - __half2float(h0));
        __half l1 = __float2half_rn(v.y - __half2float(h1));
        __half l2 = __float2half_rn(v.z - __half2float(h2));
        __half l3 = __float2half_rn(v.w - __half2float(h3));
        uint32_t off = xswz(r, c);
        *(uint2*)(a_hi + off) = make_uint2((uint32_t)h_us(h0) | ((uint32_t)h_us(h1) << 16),
                                           (uint32_t)h_us(h2) | ((uint32_t)h_us(h3) << 16));
        *(uint2*)(a_lo + off) = make_uint2((uint32_t)h_us(l0) | ((uint32_t)h_us(l1) << 16),
                                           (uint32_t)h_us(l2) | ((uint32_t)h_us(l3) << 16));
    }
}

__device__ __forceinline__ void copy_wimg(char* dstB, int widx) {
    const uint4* s = (const uint4*)(g_wimg + (size_t)widx * 65536);
    uint4* d = (uint4*)dstB;
    #pragma unroll 4
    for (int i = threadIdx.x; i < 4096; i += 256) d[i] = s[i];  // hi+lo 64KB
}

// ---------------------------------------------------------------------------
// GEMM mainloop: warp (wid&3)->mrow, (wid>>2)->ncol; acc[2][8][4] f32.
// 3-term split: HH + HL + LH.
// ---------------------------------------------------------------------------
__device__ __forceinline__ void mma_loop(uint32_t sb, float (&acc)[2][8][4],
                                         int mrow, int ncol, int lane) {
    uint32_t sXhi = sb + SM_XHI, sXlo = sb + SM_XLO;
    uint32_t sWhi = sb + SM_WHI, sWlo = sb + SM_WLO;
    int arow = mrow + (lane & 15);
    int brow0 = ncol + (lane & 7);
    #pragma unroll
    for (int ks = 0; ks < 8; ks++) {
        int ac16 = ks * 2 + (lane >> 4);
        uint32_t aoff = (uint32_t)(arow * 256 + ((ac16 ^ (arow & 7)) << 4));
        uint32_t ah[2][4], al[2][4];
        LDSM4(ah[0], sXhi + aoff);
        LDSM4(ah[1], sXhi + aoff + 4096);   // +16 rows
        LDSM4(al[0], sXlo + aoff);
        LDSM4(al[1], sXlo + aoff + 4096);
        int bc16 = ks * 2 + ((lane >> 3) & 1);
        #pragma unroll
        for (int nf = 0; nf < 8; nf++) {
            int n = brow0 + nf * 8;
            uint32_t boff = (uint32_t)(n * 256 + ((bc16 ^ (n & 7)) << 4));
            uint32_t bh[2], bl[2];
            LDSM2(bh, sWhi + boff);
            LDSM2(bl, sWlo + boff);
            MMA(acc[0][nf], ah[0], bh);
            MMA(acc[1][nf], ah[1], bh);
            MMA(acc[0][nf], ah[0], bl);
            MMA(acc[1][nf], ah[1], bl);
            MMA(acc[0][nf], al[0], bh);
            MMA(acc[1][nf], al[1], bh);
        }
    }
}

// ---------------------------------------------------------------------------
// K1: node projections (blockIdx.y: 0 -> psrc (W_s2e), 1 -> ptgt (W_t2e))
// ---------------------------------------------------------------------------
__global__ void __launch_bounds__(256, 1) k_nodeproj(const float* __restrict__ src,
                                                     const float* __restrict__ tgt) {
    extern __shared__ char smem[];
    uint32_t sb = smem_u32(smem);
    int tid = threadIdx.x, wid = tid >> 5, lane = tid & 31;
    const float* X = (blockIdx.y == 0) ? src : tgt;
    float* O = (blockIdx.y == 0) ? g_psrc : g_ptgt;
    int r0 = blockIdx.x * TILE_M;
    copy_wimg(smem + SM_WHI, blockIdx.y);
    convert_tile(X, r0, NN, smem + SM_XHI, smem + SM_XLO);
    __syncthreads();
    int mrow = (wid & 3) * 32, ncol = (wid >> 2) * 64;
    float acc[2][8][4] = {};
    mma_loop(sb, acc, mrow, ncol, lane);
    // store: lane holds rows (mrow+mf*16+l/4 (+8)), cols ncol+nf*8+(l&3)*2
    #pragma unroll
    for (int mf = 0; mf < 2; mf++) {
        #pragma unroll
        for (int h = 0; h < 2; h++) {
            int r = mrow + mf * 16 + (lane >> 2) + h * 8;
            int n = r0 + r;
            if (n < NN) {
                #pragma unroll
                for (int nf = 0; nf < 8; nf++) {
                    int c = ncol + nf * 8 + (lane & 3) * 2;
                    *(float2*)(O + (size_t)n * D + c) =
                        make_float2(acc[mf][nf][h * 2], acc[mf][nf][h * 2 + 1]);
                }
            }
        }
    }
}

// ---------------------------------------------------------------------------
// K2: fused edge update + aggregation
// ---------------------------------------------------------------------------
__global__ void __launch_bounds__(256, 1) k_edge(
    const float* __restrict__ edge, const int* __restrict__ src_idx,
    const int* __restrict__ tgt_idx, const float* __restrict__ g1,
    const float* __restrict__ b1, float* __restrict__ edge_out) {
    extern __shared__ char smem[];
    uint32_t sb = smem_u32(smem);
    int tid = threadIdx.x, wid = tid >> 5, lane = tid & 31;
    int e0 = blockIdx.x * TILE_M;
    copy_wimg(smem + SM_WHI, 2);  // W_e2e
    convert_tile(edge, e0, NE, smem + SM_XHI, smem + SM_XLO);
    __syncthreads();
    int mrow = (wid & 3) * 32, ncol = (wid >> 2) * 64, nwarp = wid >> 2;
    float acc[2][8][4] = {};
    mma_loop(sb, acc, mrow, ncol, lane);

    float2* red = (float2*)(smem + SM_RED);   // [128][2]

    // pass 1: gather adds + silu (in place) + per-row partial sums
    #pragma unroll
    for (int mf = 0; mf < 2; mf++) {
        #pragma unroll
        for (int h = 0; h < 2; h++) {
            int r = mrow + mf * 16 + (lane >> 2) + h * 8;
            int e = e0 + r;
            bool valid = e < NE;
            int ec = valid ? e : 0;
            int si = src_idx[ec];
            int ti = tgt_idx[ec];
            const float* ps = g_psrc + (size_t)si * D;
            const float* pt = g_ptgt + (size_t)ti * D;
            float sum = 0.f, sq = 0.f;
            #pragma unroll
            for (int nf = 0; nf < 8; nf++) {
                int c = ncol + nf * 8 + (lane & 3) * 2;
                float2 pv = *(const float2*)(ps + c);
                float2 qv = *(const float2*)(pt + c);
                float s0 = silu(acc[mf][nf][h * 2]     + pv.x + qv.x);
                float s1 = silu(acc[mf][nf][h * 2 + 1] + pv.y + qv.y);
                acc[mf][nf][h * 2]     = s0;
                acc[mf][nf][h * 2 + 1] = s1;
                sum += s0 + s1;
                sq  += s0 * s0 + s1 * s1;
            }
            sum += __shfl_xor_sync(0xffffffffu, sum, 1);
            sq  += __shfl_xor_sync(0xffffffffu, sq,  1);
            sum += __shfl_xor_sync(0xffffffffu, sum, 2);
            sq  += __shfl_xor_sync(0xffffffffu, sq,  2);
            if ((lane & 3) == 0) red[r * 2 + nwarp] = make_float2(sum, sq);
        }
    }
    __syncthreads();

    // pass 2: LN + residual + store + RED aggregate
    #pragma unroll
    for (int mf = 0; mf < 2; mf++) {
        #pragma unroll
        for (int h = 0; h < 2; h++) {
            int r = mrow + mf * 16 + (lane >> 2) + h * 8;
            int e = e0 + r;
            bool valid = e < NE;
            int ec = valid ? e : 0;
            int ti = tgt_idx[ec];
            float2 pa = red[r * 2 + 0];
            float2 pb = red[r * 2 + 1];
            float mean = (pa.x + pb.x) * (1.f / D);
            float var  = (pa.y + pb.y) * (1.f / D) - mean * mean;
            float rstd = rsqrtf(var + 1e-5f);
            if (valid) {
                const float* er = edge + (size_t)e * D;
                float* eo = edge_out + (size_t)e * D;
                float* ap = g_agg + (size_t)ti * D;
                #pragma unroll
                for (int nf = 0; nf < 8; nf++) {
                    int c = ncol + nf * 8 + (lane & 3) * 2;
                    float2 gv = *(const float2*)(g1 + c);
                    float2 bv = *(const float2*)(b1 + c);
                    float2 ev = *(const float2*)(er + c);
                    float o0 = (acc[mf][nf][h * 2]     - mean) * rstd * gv.x + bv.x + ev.x;
                    float o1 = (acc[mf][nf][h * 2 + 1] - mean) * rstd * gv.y + bv.y + ev.y;
                    *(float2*)(eo + c) = make_float2(o0, o1);
                    asm volatile("red.global.add.v2.f32 [%0], {%1,%2};"
                                 :: "l"(ap + c), "f"(o0), "f"(o1) : "memory");
                }
            }
        }
    }
}

// ---------------------------------------------------------------------------
// K3: target update: acc = agg@We2t^T then += tgt@Wt2t^T, then LN epilogue
// ---------------------------------------------------------------------------
__global__ void __launch_bounds__(256, 1) k_tgt(
    const float* __restrict__ tgt, const float* __restrict__ g2,
    const float* __restrict__ b2, float* __restrict__ tgt_out) {
    extern __shared__ char smem[];
    uint32_t sb = smem_u32(smem);
    int tid = threadIdx.x, wid = tid >> 5, lane = tid & 31;
    int r0 = blockIdx.x * TILE_M;
    int mrow = (wid & 3) * 32, ncol = (wid >> 2) * 64, nwarp = wid >> 2;
    float acc[2][8][4] = {};

    copy_wimg(smem + SM_WHI, 3);
    convert_tile(g_agg, r0, NN, smem + SM_XHI, smem + SM_XLO);
    __syncthreads();
    mma_loop(sb, acc, mrow, ncol, lane);
    __syncthreads();

    copy_wimg(smem + SM_WHI, 4);
    convert_tile(tgt, r0, NN, smem + SM_XHI, smem + SM_XLO);
    __syncthreads();
    mma_loop(sb, acc, mrow, ncol, lane);

    float2* red = (float2*)(smem + SM_RED);
    __syncthreads();  // before reusing red region (overlaps nothing, but order writes)

    #pragma unroll
    for (int mf = 0; mf < 2; mf++) {
        #pragma unroll
        for (int h = 0; h < 2; h++) {
            int r = mrow + mf * 16 + (lane >> 2) + h * 8;
            float sum = 0.f, sq = 0.f;
            #pragma unroll
            for (int nf = 0; nf < 8; nf++) {
                float s0 = silu(acc[mf][nf][h * 2]);
                float s1 = silu(acc[mf][nf][h * 2 + 1]);
                acc[mf][nf][h * 2]     = s0;
                acc[mf][nf][h * 2 + 1] = s1;
                sum += s0 + s1;
                sq  += s0 * s0 + s1 * s1;
            }
            sum += __shfl_xor_sync(0xffffffffu, sum, 1);
            sq  += __shfl_xor_sync(0xffffffffu, sq,  1);
            sum += __shfl_xor_sync(0xffffffffu, sum, 2);
            sq  += __shfl_xor_sync(0xffffffffu, sq,  2);
            if ((lane & 3) == 0) red[r * 2 + nwarp] = make_float2(sum, sq);
        }
    }
    __syncthreads();

    #pragma unroll
    for (int mf = 0; mf < 2; mf++) {
        #pragma unroll
        for (int h = 0; h < 2; h++) {
            int r = mrow + mf * 16 + (lane >> 2) + h * 8;
            int n = r0 + r;
            bool valid = n < NN;
            float2 pa = red[r * 2 + 0];
            float2 pb = red[r * 2 + 1];
            float mean = (pa.x + pb.x) * (1.f / D);
            float var  = (pa.y + pb.y) * (1.f / D) - mean * mean;
            float rstd = rsqrtf(var + 1e-5f);
            if (valid) {
                const float* tr = tgt + (size_t)n * D;
                float* to = tgt_out + (size_t)n * D;
                #pragma unroll
                for (int nf = 0; nf < 8; nf++) {
                    int c = ncol + nf * 8 + (lane & 3) * 2;
                    float2 gv = *(const float2*)(g2 + c);
                    float2 bv = *(const float2*)(b2 + c);
                    float2 tv = *(const float2*)(tr + c);
                    float o0 = (acc[mf][nf][h * 2]     - mean) * rstd * gv.x + bv.x + tv.x;
                    float o1 = (acc[mf][nf][h * 2 + 1] - mean) * rstd * gv.y + bv.y + tv.y;
                    *(float2*)(to + c) = make_float2(o0, o1);
                }
            }
        }
    }
}

// ---------------------------------------------------------------------------
extern "C" void kernel_launch(void* const* d_in, const int* in_sizes, int n_in,
                              void* d_out, int out_size) {
    const float* src     = (const float*)d_in[0];
    const float* tgt     = (const float*)d_in[1];
    const float* edge    = (const float*)d_in[2];
    const int*   src_idx = (const int*)d_in[3];
    const int*   tgt_idx = (const int*)d_in[4];
    const float* W_s2e   = (const float*)d_in[5];
    const float* W_t2e   = (const float*)d_in[6];
    const float* W_e2e   = (const float*)d_in[7];
    const float* W_e2t   = (const float*)d_in[8];
    const float* W_t2t   = (const float*)d_in[9];
    const float* ln1_g   = (const float*)d_in[10];
    const float* ln1_b   = (const float*)d_in[11];
    const float* ln2_g   = (const float*)d_in[12];
    const float* ln2_b   = (const float*)d_in[13];

    float* edge_out = (float*)d_out;
    float* tgt_out  = edge_out + (size_t)NE * D;

    cudaFuncSetAttribute(k_nodeproj, cudaFuncAttributeMaxDynamicSharedMemorySize, SM_TOTAL);
    cudaFuncSetAttribute(k_edge,     cudaFuncAttributeMaxDynamicSharedMemorySize, SM_TOTAL);
    cudaFuncSetAttribute(k_tgt,      cudaFuncAttributeMaxDynamicSharedMemorySize, SM_TOTAL);

    k_zero<<<(NN * D / 4 + 255) / 256, 256>>>();
    k_prep<<<5, 256>>>(W_s2e, W_t2e, W_e2e, W_e2t, W_t2t);
    dim3 gn((NN + TILE_M - 1) / TILE_M, 2);
    k_nodeproj<<<gn, 256, SM_TOTAL>>>(src, tgt);
    k_edge<<<(NE + TILE_M - 1) / TILE_M, 256, SM_TOTAL>>>(edge, src_idx, tgt_idx,
                                                          ln1_g, ln1_b, edge_out);
    k_tgt<<<(NN + TILE_M - 1) / TILE_M, 256, SM_TOTAL>>>(tgt, ln2_g, ln2_b, tgt_out);
}

// round 5
// speedup vs baseline: 1.8395x; 1.8395x over previous
#include <cuda_runtime.h>
#include <cuda_fp16.h>
#include <cstdint>

#define D 128
#define NN 50000
#define NE 500000
#define TILE 64                     // X-tile rows per CTA

// ---------------- scratch (__device__ globals) ------------------------------
__device__ float g_psrc[(size_t)NN * D];
__device__ float g_ptgt[(size_t)NN * D];
__device__ float g_agg [(size_t)NN * D];
// fp16 hi/lo weight images in the exact swizzled smem layout: [5][hi 32KB][lo 32KB]
__device__ unsigned char g_wimg[5 * 65536];

// ---------------- smem layout (per CTA, ~97.5KB -> 2 CTAs/SM) ---------------
#define SM_XHI 0                    // 64 rows * 256B = 16KB
#define SM_XLO 16384
#define SM_WHI 32768                // 128 rows * 256B = 32KB
#define SM_WLO 65536
#define SM_RED 98304                // float2 red[64][2] = 1KB
#define SM_TOTAL (98304 + 1024)

// swizzled fp16 tile: row r x col c; 256B/row, 16B chunks; chunk ^= (r&7)
__device__ __forceinline__ uint32_t xswz(int r, int c) {
    return (uint32_t)(r * 256 + (((c >> 3) ^ (r & 7)) << 4) + (c & 7) * 2);
}

#define LDSM4(r, a) \
    asm volatile("ldmatrix.sync.aligned.m8n8.x4.shared.b16 {%0,%1,%2,%3}, [%4];" \
        : "=r"((r)[0]), "=r"((r)[1]), "=r"((r)[2]), "=r"((r)[3]) : "r"(a))
#define LDSM2(r, a) \
    asm volatile("ldmatrix.sync.aligned.m8n8.x2.shared.b16 {%0,%1}, [%2];" \
        : "=r"((r)[0]), "=r"((r)[1]) : "r"(a))
#define MMA(c, a, b) \
    asm volatile("mma.sync.aligned.m16n8k16.row.col.f32.f16.f16.f32 " \
        "{%0,%1,%2,%3}, {%4,%5,%6,%7}, {%8,%9}, {%0,%1,%2,%3};" \
        : "+f"((c)[0]), "+f"((c)[1]), "+f"((c)[2]), "+f"((c)[3]) \
        : "r"((a)[0]), "r"((a)[1]), "r"((a)[2]), "r"((a)[3]), "r"((b)[0]), "r"((b)[1]))

__device__ __forceinline__ uint32_t smem_u32(const void* p) {
    uint32_t a;
    asm("{ .reg .u64 t; cvta.to.shared.u64 t, %1; cvt.u32.u64 %0, t; }" : "=r"(a) : "l"(p));
    return a;
}
__device__ __forceinline__ unsigned short h_us(__half h) { return __half_as_ushort(h); }
__device__ __forceinline__ float silu(float m) { return m * (1.f / (1.f + __expf(-m))); }

// ---------------------------------------------------------------------------
__global__ void k_zero() {
    size_t i = ((size_t)blockIdx.x * blockDim.x + threadIdx.x) * 4;
    if (i < (size_t)NN * D) *(float4*)(g_agg + i) = make_float4(0.f, 0.f, 0.f, 0.f);
}

// prep: W [N,K] row-major -> swizzled fp16 hi/lo images (B operand, K-major)
__global__ void k_prep(const float* __restrict__ s2e, const float* __restrict__ t2e,
                       const float* __restrict__ e2e, const float* __restrict__ e2t,
                       const float* __restrict__ t2t) {
    const float* W[5] = {s2e, t2e, e2e, e2t, t2t};
    const float* src = W[blockIdx.x];
    unsigned char* hi = g_wimg + (size_t)blockIdx.x * 65536;
    unsigned char* lo = hi + 32768;
    for (int i = threadIdx.x; i < D * D; i += blockDim.x) {
        int n = i >> 7, k = i & 127;
        float w = src[i];
        __half h = __float2half_rn(w);
        __half l = __float2half_rn(w - __half2float(h));
        uint32_t off = xswz(n, k);
        *(__half*)(hi + off) = h;
        *(__half*)(lo + off) = l;
    }
}

// convert fp32 tile [TILE x 128] -> split hi/lo fp16 in swizzled smem
__device__ __forceinline__ void convert_tile(const float* __restrict__ src, int row0,
                                             int nrows, char* a_hi, char* a_lo) {
    #pragma unroll
    for (int it = 0; it < 8; it++) {
        int i = threadIdx.x + it * 256;      // TILE*32 = 2048 float4 slots
        int r = i >> 5;
        int c = (i & 31) << 2;
        float4 v = make_float4(0.f, 0.f, 0.f, 0.f);
        if (row0 + r < nrows) v = *(const float4*)(src + (size_t)(row0 + r) * D + c);
        __half h0 = __float2half_rn(v.x), h1 = __float2half_rn(v.y);
        __half h2 = __float2half_rn(v.z), h3 = __float2half_rn(v.w);
        __half l0 = __float2half_rn(v.x - __half2float(h0));
        __half l1 = __float2half_rn(v.y - __half2float(h1));
        __half l2 = __float2half_rn(v.z - __half2float(h2));
        __half l3 = __float2half_rn(v.w - __half2float(h3));
        uint32_t off = xswz(r, c);
        *(uint2*)(a_hi + off) = make_uint2((uint32_t)h_us(h0) | ((uint32_t)h_us(h1) << 16),
                                           (uint32_t)h_us(h2) | ((uint32_t)h_us(h3) << 16));
        *(uint2*)(a_lo + off) = make_uint2((uint32_t)h_us(l0) | ((uint32_t)h_us(l1) << 16),
                                           (uint32_t)h_us(l2) | ((uint32_t)h_us(l3) << 16));
    }
}

__device__ __forceinline__ void copy_wimg(char* dstB, int widx) {
    const uint4* s = (const uint4*)(g_wimg + (size_t)widx * 65536);
    uint4* d = (uint4*)dstB;
    #pragma unroll 4
    for (int i = threadIdx.x; i < 4096; i += 256) d[i] = s[i];  // hi+lo 64KB
}

// ---------------------------------------------------------------------------
// GEMM mainloop: 8 warps = 4(M) x 2(N); warp tile 16 x 64; acc[8][4] f32.
// 3-term split: HH + HL + LH.
// ---------------------------------------------------------------------------
__device__ __forceinline__ void mma_loop(uint32_t sb, float (&acc)[8][4],
                                         int mrow, int ncol, int lane) {
    uint32_t sXhi = sb + SM_XHI, sXlo = sb + SM_XLO;
    uint32_t sWhi = sb + SM_WHI, sWlo = sb + SM_WLO;
    int arow = mrow + (lane & 15);
    int brow0 = ncol + (lane & 7);
    #pragma unroll
    for (int ks = 0; ks < 8; ks++) {
        int ac16 = ks * 2 + (lane >> 4);
        uint32_t aoff = (uint32_t)(arow * 256 + ((ac16 ^ (arow & 7)) << 4));
        uint32_t ah[4], al[4];
        LDSM4(ah, sXhi + aoff);
        LDSM4(al, sXlo + aoff);
        int bc16 = ks * 2 + ((lane >> 3) & 1);
        #pragma unroll
        for (int nf = 0; nf < 8; nf++) {
            int n = brow0 + nf * 8;
            uint32_t boff = (uint32_t)(n * 256 + ((bc16 ^ (n & 7)) << 4));
            uint32_t bh[2], bl[2];
            LDSM2(bh, sWhi + boff);
            LDSM2(bl, sWlo + boff);
            MMA(acc[nf], ah, bh);
            MMA(acc[nf], ah, bl);
            MMA(acc[nf], al, bh);
        }
    }
}

// ---------------------------------------------------------------------------
// K1: node projections (blockIdx.y: 0 -> psrc (W_s2e), 1 -> ptgt (W_t2e))
// ---------------------------------------------------------------------------
__global__ void __launch_bounds__(256, 2) k_nodeproj(const float* __restrict__ src,
                                                     const float* __restrict__ tgt) {
    extern __shared__ char smem[];
    uint32_t sb = smem_u32(smem);
    int tid = threadIdx.x, wid = tid >> 5, lane = tid & 31;
    const float* X = (blockIdx.y == 0) ? src : tgt;
    float* O = (blockIdx.y == 0) ? g_psrc : g_ptgt;
    int r0 = blockIdx.x * TILE;
    copy_wimg(smem + SM_WHI, blockIdx.y);
    convert_tile(X, r0, NN, smem + SM_XHI, smem + SM_XLO);
    __syncthreads();
    int mrow = (wid & 3) * 16, ncol = (wid >> 2) * 64;
    float acc[8][4] = {};
    mma_loop(sb, acc, mrow, ncol, lane);
    #pragma unroll
    for (int h = 0; h < 2; h++) {
        int n = r0 + mrow + (lane >> 2) + h * 8;
        if (n < NN) {
            #pragma unroll
            for (int nf = 0; nf < 8; nf++) {
                int c = ncol + nf * 8 + (lane & 3) * 2;
                *(float2*)(O + (size_t)n * D + c) =
                    make_float2(acc[nf][h * 2], acc[nf][h * 2 + 1]);
            }
        }
    }
}

// ---------------------------------------------------------------------------
// K2: fused edge update + aggregation
// ---------------------------------------------------------------------------
__global__ void __launch_bounds__(256, 2) k_edge(
    const float* __restrict__ edge, const int* __restrict__ src_idx,
    const int* __restrict__ tgt_idx, const float* __restrict__ g1,
    const float* __restrict__ b1, float* __restrict__ edge_out) {
    extern __shared__ char smem[];
    uint32_t sb = smem_u32(smem);
    int tid = threadIdx.x, wid = tid >> 5, lane = tid & 31;
    int e0 = blockIdx.x * TILE;
    copy_wimg(smem + SM_WHI, 2);  // W_e2e
    convert_tile(edge, e0, NE, smem + SM_XHI, smem + SM_XLO);
    __syncthreads();
    int mrow = (wid & 3) * 16, ncol = (wid >> 2) * 64, nwarp = wid >> 2;
    float acc[8][4] = {};
    mma_loop(sb, acc, mrow, ncol, lane);

    float2* red = (float2*)(smem + SM_RED);   // [64][2]

    // pass 1: gather adds + silu (in place) + per-row partial sums
    #pragma unroll
    for (int h = 0; h < 2; h++) {
        int r = mrow + (lane >> 2) + h * 8;
        int e = e0 + r;
        bool valid = e < NE;
        int ec = valid ? e : 0;
        int si = src_idx[ec];
        int ti = tgt_idx[ec];
        const float* ps = g_psrc + (size_t)si * D;
        const float* pt = g_ptgt + (size_t)ti * D;
        float sum = 0.f, sq = 0.f;
        #pragma unroll
        for (int nf = 0; nf < 8; nf++) {
            int c = ncol + nf * 8 + (lane & 3) * 2;
            float2 pv = *(const float2*)(ps + c);
            float2 qv = *(const float2*)(pt + c);
            float s0 = silu(acc[nf][h * 2]     + pv.x + qv.x);
            float s1 = silu(acc[nf][h * 2 + 1] + pv.y + qv.y);
            acc[nf][h * 2]     = s0;
            acc[nf][h * 2 + 1] = s1;
            sum += s0 + s1;
            sq  += s0 * s0 + s1 * s1;
        }
        sum += __shfl_xor_sync(0xffffffffu, sum, 1);
        sq  += __shfl_xor_sync(0xffffffffu, sq,  1);
        sum += __shfl_xor_sync(0xffffffffu, sum, 2);
        sq  += __shfl_xor_sync(0xffffffffu, sq,  2);
        if ((lane & 3) == 0) red[r * 2 + nwarp] = make_float2(sum, sq);
    }
    __syncthreads();

    // pass 2: LN + residual + store + RED aggregate
    #pragma unroll
    for (int h = 0; h < 2; h++) {
        int r = mrow + (lane >> 2) + h * 8;
        int e = e0 + r;
        bool valid = e < NE;
        int ec = valid ? e : 0;
        int ti = tgt_idx[ec];
        float2 pa = red[r * 2 + 0];
        float2 pb = red[r * 2 + 1];
        float mean = (pa.x + pb.x) * (1.f / D);
        float var  = (pa.y + pb.y) * (1.f / D) - mean * mean;
        float rstd = rsqrtf(var + 1e-5f);
        if (valid) {
            const float* er = edge + (size_t)e * D;
            float* eo = edge_out + (size_t)e * D;
            float* ap = g_agg + (size_t)ti * D;
            #pragma unroll
            for (int nf = 0; nf < 8; nf++) {
                int c = ncol + nf * 8 + (lane & 3) * 2;
                float2 gv = *(const float2*)(g1 + c);
                float2 bv = *(const float2*)(b1 + c);
                float2 ev = *(const float2*)(er + c);
                float o0 = (acc[nf][h * 2]     - mean) * rstd * gv.x + bv.x + ev.x;
                float o1 = (acc[nf][h * 2 + 1] - mean) * rstd * gv.y + bv.y + ev.y;
                *(float2*)(eo + c) = make_float2(o0, o1);
                asm volatile("red.global.add.v2.f32 [%0], {%1,%2};"
                             :: "l"(ap + c), "f"(o0), "f"(o1) : "memory");
            }
        }
    }
}

// ---------------------------------------------------------------------------
// K3: target update: acc = agg@We2t^T then += tgt@Wt2t^T, then LN epilogue
// ---------------------------------------------------------------------------
__global__ void __launch_bounds__(256, 2) k_tgt(
    const float* __restrict__ tgt, const float* __restrict__ g2,
    const float* __restrict__ b2, float* __restrict__ tgt_out) {
    extern __shared__ char smem[];
    uint32_t sb = smem_u32(smem);
    int tid = threadIdx.x, wid = tid >> 5, lane = tid & 31;
    int r0 = blockIdx.x * TILE;
    int mrow = (wid & 3) * 16, ncol = (wid >> 2) * 64, nwarp = wid >> 2;
    float acc[8][4] = {};

    copy_wimg(smem + SM_WHI, 3);
    convert_tile(g_agg, r0, NN, smem + SM_XHI, smem + SM_XLO);
    __syncthreads();
    mma_loop(sb, acc, mrow, ncol, lane);
    __syncthreads();

    copy_wimg(smem + SM_WHI, 4);
    convert_tile(tgt, r0, NN, smem + SM_XHI, smem + SM_XLO);
    __syncthreads();
    mma_loop(sb, acc, mrow, ncol, lane);

    float2* red = (float2*)(smem + SM_RED);
    __syncthreads();

    #pragma unroll
    for (int h = 0; h < 2; h++) {
        int r = mrow + (lane >> 2) + h * 8;
        float sum = 0.f, sq = 0.f;
        #pragma unroll
        for (int nf = 0; nf < 8; nf++) {
            float s0 = silu(acc[nf][h * 2]);
            float s1 = silu(acc[nf][h * 2 + 1]);
            acc[nf][h * 2]     = s0;
            acc[nf][h * 2 + 1] = s1;
            sum += s0 + s1;
            sq  += s0 * s0 + s1 * s1;
        }
        sum += __shfl_xor_sync(0xffffffffu, sum, 1);
        sq  += __shfl_xor_sync(0xffffffffu, sq,  1);
        sum += __shfl_xor_sync(0xffffffffu, sum, 2);
        sq  += __shfl_xor_sync(0xffffffffu, sq,  2);
        if ((lane & 3) == 0) red[r * 2 + nwarp] = make_float2(sum, sq);
    }
    __syncthreads();

    #pragma unroll
    for (int h = 0; h < 2; h++) {
        int r = mrow + (lane >> 2) + h * 8;
        int n = r0 + r;
        float2 pa = red[r * 2 + 0];
        float2 pb = red[r * 2 + 1];
        float mean = (pa.x + pb.x) * (1.f / D);
        float var  = (pa.y + pb.y) * (1.f / D) - mean * mean;
        float rstd = rsqrtf(var + 1e-5f);
        if (n < NN) {
            const float* tr = tgt + (size_t)n * D;
            float* to = tgt_out + (size_t)n * D;
            #pragma unroll
            for (int nf = 0; nf < 8; nf++) {
                int c = ncol + nf * 8 + (lane & 3) * 2;
                float2 gv = *(const float2*)(g2 + c);
                float2 bv = *(const float2*)(b2 + c);
                float2 tv = *(const float2*)(tr + c);
                float o0 = (acc[nf][h * 2]     - mean) * rstd * gv.x + bv.x + tv.x;
                float o1 = (acc[nf][h * 2 + 1] - mean) * rstd * gv.y + bv.y + tv.y;
                *(float2*)(to + c) = make_float2(o0, o1);
            }
        }
    }
}

// ---------------------------------------------------------------------------
extern "C" void kernel_launch(void* const* d_in, const int* in_sizes, int n_in,
                              void* d_out, int out_size) {
    const float* src     = (const float*)d_in[0];
    const float* tgt     = (const float*)d_in[1];
    const float* edge    = (const float*)d_in[2];
    const int*   src_idx = (const int*)d_in[3];
    const int*   tgt_idx = (const int*)d_in[4];
    const float* W_s2e   = (const float*)d_in[5];
    const float* W_t2e   = (const float*)d_in[6];
    const float* W_e2e   = (const float*)d_in[7];
    const float* W_e2t   = (const float*)d_in[8];
    const float* W_t2t   = (const float*)d_in[9];
    const float* ln1_g   = (const float*)d_in[10];
    const float* ln1_b   = (const float*)d_in[11];
    const float* ln2_g   = (const float*)d_in[12];
    const float* ln2_b   = (const float*)d_in[13];

    float* edge_out = (float*)d_out;
    float* tgt_out  = edge_out + (size_t)NE * D;

    cudaFuncSetAttribute(k_nodeproj, cudaFuncAttributeMaxDynamicSharedMemorySize, SM_TOTAL);
    cudaFuncSetAttribute(k_edge,     cudaFuncAttributeMaxDynamicSharedMemorySize, SM_TOTAL);
    cudaFuncSetAttribute(k_tgt,      cudaFuncAttributeMaxDynamicSharedMemorySize, SM_TOTAL);

    k_zero<<<(NN * D / 4 + 255) / 256, 256>>>();
    k_prep<<<5, 256>>>(W_s2e, W_t2e, W_e2e, W_e2t, W_t2t);
    dim3 gn((NN + TILE - 1) / TILE, 2);
    k_nodeproj<<<gn, 256, SM_TOTAL>>>(src, tgt);
    k_edge<<<(NE + TILE - 1) / TILE, 256, SM_TOTAL>>>(edge, src_idx, tgt_idx,
                                                      ln1_g, ln1_b, edge_out);
    k_tgt<<<(NN + TILE - 1) / TILE, 256, SM_TOTAL>>>(tgt, ln2_g, ln2_b, tgt_out);
}